// round 12
// baseline (speedup 1.0000x reference)
#include <cuda_runtime.h>
#include <cuda_fp16.h>
#include <math.h>
#include <stdint.h>

#define Bn 4
#define Tn 2048
#define Cn 2048
#define NHEAD 16
#define NKV 4
#define HD 128
#define NREP 4
#define GK 2048

// ---------------- scratch (device globals) ----------------
__device__ __half g_xhi[(size_t)Bn * Tn * Cn];   // x-split; reused as y-split after flash
__device__ __half g_xlo[(size_t)Bn * Tn * Cn];
__device__ __half g_qhi[(size_t)Bn * Tn * Cn];
__device__ __half g_qlo[(size_t)Bn * Tn * Cn];
__device__ __half g_k16[(size_t)Bn * Tn * NKV * HD];
__device__ __half g_v16[(size_t)Bn * Tn * NKV * HD];

#define WQ_OFF ((size_t)0)
#define WK_OFF ((size_t)2048 * 2048)
#define WV_OFF (WK_OFF + (size_t)512 * 2048)
#define WO_OFF (WV_OFF + (size_t)512 * 2048)
#define WT_TOTAL (WO_OFF + (size_t)2048 * 2048)
__device__ __half g_wT[WT_TOTAL];

// ================= base-ISA helpers =================
__device__ __forceinline__ uint32_t smem_u32(const void* p) {
    uint32_t a;
    asm("{ .reg .u64 t; cvta.to.shared.u64 t, %1; cvt.u32.u64 %0, t; }" : "=r"(a) : "l"(p));
    return a;
}
__device__ __forceinline__ void cp16(uint32_t dst, const void* src) {
    asm volatile("cp.async.cg.shared.global [%0], [%1], 16;" :: "r"(dst), "l"(src) : "memory");
}
__device__ __forceinline__ void cp_commit() { asm volatile("cp.async.commit_group;" ::: "memory"); }
__device__ __forceinline__ void cp_wait0()  { asm volatile("cp.async.wait_group 0;" ::: "memory"); }
__device__ __forceinline__ void cp_wait1()  { asm volatile("cp.async.wait_group 1;" ::: "memory"); }
__device__ __forceinline__ float ex2f(float x) {
    float r; asm("ex2.approx.ftz.f32 %0, %1;" : "=f"(r) : "f"(x)); return r;
}

#define SW128(o) ((o) ^ (((o) >> 3) & 0x70))

#define LDSM4(r0, r1, r2, r3, addr)                                             \
    asm volatile("ldmatrix.sync.aligned.m8n8.x4.shared.b16 {%0,%1,%2,%3}, [%4];" \
                 : "=r"(r0), "=r"(r1), "=r"(r2), "=r"(r3) : "r"(addr))

#define LDSMT4(r0, r1, r2, r3, addr)                                            \
    asm volatile("ldmatrix.sync.aligned.m8n8.x4.trans.shared.b16 {%0,%1,%2,%3}, [%4];" \
                 : "=r"(r0), "=r"(r1), "=r"(r2), "=r"(r3) : "r"(addr))

#define MMA16816(d, a, b0, b1)                                                  \
    asm volatile("mma.sync.aligned.m16n8k16.row.col.f32.f16.f16.f32 "           \
                 "{%0,%1,%2,%3},{%4,%5,%6,%7},{%8,%9},{%0,%1,%2,%3};"           \
                 : "+f"((d)[0]), "+f"((d)[1]), "+f"((d)[2]), "+f"((d)[3])       \
                 : "r"((a)[0]), "r"((a)[1]), "r"((a)[2]), "r"((a)[3]),          \
                   "r"(b0), "r"(b1))

#define PACK2H(r, hiv, lov) \
    asm("cvt.rn.f16x2.f32 %0, %1, %2;" : "=r"(r) : "f"(hiv), "f"(lov))

__device__ __forceinline__ void pack_splith(float p0, float p1, uint32_t& h, uint32_t& l) {
    PACK2H(h, p1, p0);
    float h0 = __half2float(__ushort_as_half((unsigned short)(h & 0xffffu)));
    float h1 = __half2float(__ushort_as_half((unsigned short)(h >> 16)));
    PACK2H(l, p1 - h1, p0 - h0);
}

// ================= conversion kernels =================
__global__ void fsplit_kernel(const float* __restrict__ a, __half* __restrict__ hi,
                              __half* __restrict__ lo, size_t n) {
    size_t i = (size_t)blockIdx.x * blockDim.x + threadIdx.x;
    size_t stride = (size_t)gridDim.x * blockDim.x;
    for (; i < n; i += stride) {
        float v = a[i];
        __half h = __float2half_rn(v);
        hi[i] = h;
        lo[i] = __float2half_rn(v - __half2float(h));
    }
}

__global__ void wT_kernel(const float* __restrict__ w, __half* __restrict__ wT, int K, int N) {
    __shared__ float tile[32][33];
    int n0 = blockIdx.x * 32;
    int k0 = blockIdx.y * 32;
    int tx = threadIdx.x, ty = threadIdx.y;
#pragma unroll
    for (int i = ty; i < 32; i += 8)
        tile[i][tx] = w[(size_t)(k0 + i) * N + n0 + tx];
    __syncthreads();
#pragma unroll
    for (int i = ty; i < 32; i += 8)
        wT[(size_t)(n0 + i) * K + k0 + tx] = __float2half_rn(tile[tx][i]);
}

// ================= warp-MMA GEMM, 2-term (A-split x B-single), fused epilogues =======
// MODE 0: f32 out. MODE 1: RoPE+scale+split fp16. MODE 2: RoPE+single fp16. MODE 3: single fp16.
#define KCH 64
#define NCHUNK (GK / KCH)
#define TILEB (128 * 128)
#define STAGEB (3 * TILEB)
#define GM_SMEM (2 * STAGEB)              // 96 KB

template<int MODE>
__global__ __launch_bounds__(256, 2)
void gemm2_kernel(const __half* __restrict__ Ahi, const __half* __restrict__ Alo,
                  const __half* __restrict__ Bt,
                  float* __restrict__ Cf, __half* __restrict__ Ch, __half* __restrict__ Cl,
                  int Nld, const float* __restrict__ fc, float scale) {
    extern __shared__ char smem[];
    const uint32_t sb = smem_u32(smem);
    const int tid = threadIdx.x;
    const int wid = tid >> 5, lane = tid & 31;
    const int wm = wid >> 1, wn = wid & 1;
    const int m0 = blockIdx.y * 128;
    const int n0 = blockIdx.x * 128;

    const int cr = tid >> 1, chalf = tid & 1;
    const char* srcA_h = (const char*)(Ahi + (size_t)(m0 + cr) * GK);
    const char* srcA_l = (const char*)(Alo + (size_t)(m0 + cr) * GK);
    const char* srcB   = (const char*)(Bt  + (size_t)(n0 + cr) * GK);

    auto load_chunk = [&](int kc, int stage) {
        uint32_t base = sb + stage * STAGEB;
        size_t go = (size_t)kc * 128 + chalf * 64;
#pragma unroll
        for (int s = 0; s < 4; ++s) {
            uint32_t off = SW128((uint32_t)(cr * 128 + chalf * 64 + s * 16));
            cp16(base + off,             srcA_h + go + s * 16);
            cp16(base + TILEB + off,     srcA_l + go + s * 16);
            cp16(base + 2 * TILEB + off, srcB   + go + s * 16);
        }
        cp_commit();
    };

    float acc[2][8][4];
#pragma unroll
    for (int mt = 0; mt < 2; ++mt)
#pragma unroll
        for (int nt = 0; nt < 8; ++nt)
#pragma unroll
            for (int e = 0; e < 4; ++e) acc[mt][nt][e] = 0.f;

    load_chunk(0, 0);

    for (int i = 0; i < NCHUNK; ++i) {
        const int stage = i & 1;
        if (i + 1 < NCHUNK) { load_chunk(i + 1, (i + 1) & 1); cp_wait1(); }
        else                { cp_wait0(); }
        __syncthreads();

        const uint32_t bA_h = sb + stage * STAGEB;
        const uint32_t bA_l = bA_h + TILEB;
        const uint32_t bB   = bA_h + 2 * TILEB;

#pragma unroll
        for (int kk = 0; kk < 4; ++kk) {
            uint32_t ah[2][4], al[2][4];
#pragma unroll
            for (int mt = 0; mt < 2; ++mt) {
                uint32_t row = wm * 32 + mt * 16 + (lane & 15);
                uint32_t off = SW128(row * 128u + kk * 32u + ((lane >> 4) << 4));
                LDSM4(ah[mt][0], ah[mt][1], ah[mt][2], ah[mt][3], bA_h + off);
                LDSM4(al[mt][0], al[mt][1], al[mt][2], al[mt][3], bA_l + off);
            }
#pragma unroll
            for (int ntp = 0; ntp < 4; ++ntp) {
                uint32_t q = lane >> 3;
                uint32_t row = wn * 64 + ntp * 16 + ((q >> 1) << 3) + (lane & 7);
                uint32_t off = SW128(row * 128u + kk * 32u + ((q & 1) << 4));
                uint32_t bh[4];
                LDSM4(bh[0], bh[1], bh[2], bh[3], bB + off);
#pragma unroll
                for (int mt = 0; mt < 2; ++mt) {
#pragma unroll
                    for (int j = 0; j < 2; ++j) {
                        int nt = ntp * 2 + j;
                        MMA16816(acc[mt][nt], ah[mt], bh[2 * j], bh[2 * j + 1]);
                        MMA16816(acc[mt][nt], al[mt], bh[2 * j], bh[2 * j + 1]);
                    }
                }
            }
        }
        __syncthreads();
    }

    const int groupID = lane >> 2, tid4 = lane & 3;
#pragma unroll
    for (int mt = 0; mt < 2; ++mt) {
#pragma unroll
        for (int nt = 0; nt < 8; ++nt) {
            int row = m0 + wm * 32 + mt * 16 + groupID;
            int col = n0 + wn * 64 + nt * 8 + tid4 * 2;
            float v0a = acc[mt][nt][0], v1a = acc[mt][nt][1];
            float v0b = acc[mt][nt][2], v1b = acc[mt][nt][3];
            if (MODE == 0) {
                *(float2*)&Cf[(size_t)row * Nld + col]       = make_float2(v0a, v1a);
                *(float2*)&Cf[(size_t)(row + 8) * Nld + col] = make_float2(v0b, v1b);
            } else {
                if (MODE == 1 || MODE == 2) {
                    int p = (col & 127) >> 1;
                    int t0 = row & (Tn - 1);
                    float2 cs0 = *(const float2*)(fc + ((size_t)t0 * 64 + p) * 2);
                    float2 cs1 = *(const float2*)(fc + ((size_t)(t0 + 8) * 64 + p) * 2);
                    float r0 = (v0a * cs0.x - v1a * cs0.y) * scale;
                    float r1 = (v0a * cs0.y + v1a * cs0.x) * scale;
                    v0a = r0; v1a = r1;
                    r0 = (v0b * cs1.x - v1b * cs1.y) * scale;
                    r1 = (v0b * cs1.y + v1b * cs1.x) * scale;
                    v0b = r0; v1b = r1;
                }
                size_t o0 = ((size_t)row * Nld + col) * 2;
                size_t o1 = ((size_t)(row + 8) * Nld + col) * 2;
                if (MODE == 1) {
                    uint32_t hbits, lbits;
                    pack_splith(v0a, v1a, hbits, lbits);
                    *(uint32_t*)((char*)Ch + o0) = hbits;
                    *(uint32_t*)((char*)Cl + o0) = lbits;
                    pack_splith(v0b, v1b, hbits, lbits);
                    *(uint32_t*)((char*)Ch + o1) = hbits;
                    *(uint32_t*)((char*)Cl + o1) = lbits;
                } else {
                    uint32_t hb;
                    PACK2H(hb, v1a, v0a);
                    *(uint32_t*)((char*)Ch + o0) = hb;
                    PACK2H(hb, v1b, v0b);
                    *(uint32_t*)((char*)Ch + o1) = hb;
                }
            }
        }
    }
}

// ================= tensor-core flash attention (fp16; QK 2-term, PV 1-term) ===========
// Br=64 (4 warps x 16 rows), Bc=64, 128 threads, 2 CTAs/SM.
// smem: Qh 16KB @0 (2 panels x [64][128B]), Ql 16KB @16384,
//       stages @32768: { K 16KB, V 16KB } x 2 = 64KB.  Total 96KB.
#define FL_STG 32768
#define FL_SMEM (32768 + 2 * FL_STG)   // 98304

__global__ __launch_bounds__(128, 2)
void flash2_kernel(const __half* __restrict__ qh_, const __half* __restrict__ ql_,
                   const __half* __restrict__ k_, const __half* __restrict__ v_,
                   __half* __restrict__ Yh, __half* __restrict__ Yl) {
    extern __shared__ char smf[];
    const uint32_t sb = smem_u32(smf);
    const int tid = threadIdx.x;
    const int lane = tid & 31, w = tid >> 5;     // 4 warps
    const int qt = gridDim.x - 1 - blockIdx.x;   // heavy causal tiles first
    const int bh = blockIdx.y;
    const int b = bh >> 4, h = bh & 15, g = h >> 2;

    // ---- async load Q (64 rows x 128 fp16, hi+lo) ----
    {
        int r = tid >> 1, half = tid & 1;        // r: 0..63, half: panel
        size_t rowg = (size_t)(b * Tn + qt * 64 + r);
        const char* sqh = (const char*)(qh_ + (rowg * NHEAD + h) * HD + half * 64);
        const char* sql = (const char*)(ql_ + (rowg * NHEAD + h) * HD + half * 64);
        uint32_t dstH = sb + half * 8192;
        uint32_t dstL = sb + 16384 + half * 8192;
#pragma unroll
        for (int s = 0; s < 8; ++s) {
            uint32_t o = SW128((uint32_t)(r * 128 + s * 16));
            cp16(dstH + o, sqh + s * 16);
            cp16(dstL + o, sql + s * 16);
        }
    }

    auto loadkv = [&](int kt, int st) {
        int r = tid >> 1, half = tid & 1;
        size_t rowg = (size_t)(b * Tn + kt * 64 + r);
        size_t eo = (rowg * NKV + g) * HD + half * 64;
        const char* sK = (const char*)(k_ + eo);
        const char* sV = (const char*)(v_ + eo);
        uint32_t base = sb + 32768 + st * FL_STG + half * 8192;
#pragma unroll
        for (int s = 0; s < 8; ++s) {
            uint32_t o = SW128((uint32_t)(r * 128 + s * 16));
            cp16(base + o,         sK + s * 16);
            cp16(base + 16384 + o, sV + s * 16);
        }
        cp_commit();
    };

    float o[16][4];
#pragma unroll
    for (int i = 0; i < 16; ++i)
#pragma unroll
        for (int e = 0; e < 4; ++e) o[i][e] = 0.f;
    float m0 = -1e30f, m1 = -1e30f, l0 = 0.f, l1 = 0.f;

    loadkv(0, 0);
    const int nch = qt + 1;

    for (int kt = 0; kt < nch; ++kt) {
        const int st = kt & 1;
        if (kt + 1 < nch) { loadkv(kt + 1, (kt + 1) & 1); cp_wait1(); }
        else              { cp_wait0(); }
        __syncthreads();

        const uint32_t stg = sb + 32768 + st * FL_STG;

        // ---- S = Q K^T (2-term: Qh*K + Ql*K), 16 rows x 64 keys per warp ----
        float sc[8][4];
#pragma unroll
        for (int nt = 0; nt < 8; ++nt)
#pragma unroll
            for (int e = 0; e < 4; ++e) sc[nt][e] = 0.f;

#pragma unroll
        for (int kk = 0; kk < 8; ++kk) {
            const uint32_t panel = kk >> 2;
            const uint32_t pb = (kk & 3) * 32;
            uint32_t arow = w * 16 + ((lane >> 3) & 1) * 8 + (lane & 7);
            uint32_t aoff = panel * 8192 + SW128(arow * 128 + pb + (lane >> 4) * 16);
            uint32_t ah[4], al[4];
            LDSM4(ah[0], ah[1], ah[2], ah[3], sb + aoff);
            LDSM4(al[0], al[1], al[2], al[3], sb + 16384 + aoff);
#pragma unroll
            for (int nq = 0; nq < 4; ++nq) {
                uint32_t krow = nq * 16 + (lane >> 4) * 8 + (lane & 7);
                uint32_t koff = panel * 8192 + SW128(krow * 128 + pb + ((lane >> 3) & 1) * 16);
                uint32_t kh[4];
                LDSM4(kh[0], kh[1], kh[2], kh[3], stg + koff);
                MMA16816(sc[2 * nq],     ah, kh[0], kh[1]);
                MMA16816(sc[2 * nq],     al, kh[0], kh[1]);
                MMA16816(sc[2 * nq + 1], ah, kh[2], kh[3]);
                MMA16816(sc[2 * nq + 1], al, kh[2], kh[3]);
            }
        }

        // ---- causal mask (diag chunk only) ----
        if (kt == qt) {
            const int qi0 = qt * 64 + w * 16 + (lane >> 2);
            const int cb = kt * 64 + (lane & 3) * 2;
#pragma unroll
            for (int nt = 0; nt < 8; ++nt) {
#pragma unroll
                for (int e = 0; e < 4; ++e) {
                    int col = cb + nt * 8 + (e & 1);
                    int qi = qi0 + (e >> 1) * 8;
                    if (col > qi) sc[nt][e] = -1e30f;
                }
            }
        }

        // ---- online softmax (log2 domain) ----
        float mx0 = -1e30f, mx1 = -1e30f;
#pragma unroll
        for (int nt = 0; nt < 8; ++nt) {
            mx0 = fmaxf(mx0, fmaxf(sc[nt][0], sc[nt][1]));
            mx1 = fmaxf(mx1, fmaxf(sc[nt][2], sc[nt][3]));
        }
        mx0 = fmaxf(mx0, __shfl_xor_sync(0xffffffffu, mx0, 1));
        mx0 = fmaxf(mx0, __shfl_xor_sync(0xffffffffu, mx0, 2));
        mx1 = fmaxf(mx1, __shfl_xor_sync(0xffffffffu, mx1, 1));
        mx1 = fmaxf(mx1, __shfl_xor_sync(0xffffffffu, mx1, 2));

        float mn0 = fmaxf(m0, mx0), mn1 = fmaxf(m1, mx1);
        float f0 = ex2f(m0 - mn0), f1 = ex2f(m1 - mn1);
        m0 = mn0; m1 = mn1;

        float ls0 = 0.f, ls1 = 0.f;
#pragma unroll
        for (int nt = 0; nt < 8; ++nt) {
            sc[nt][0] = ex2f(sc[nt][0] - m0);
            sc[nt][1] = ex2f(sc[nt][1] - m0);
            sc[nt][2] = ex2f(sc[nt][2] - m1);
            sc[nt][3] = ex2f(sc[nt][3] - m1);
            ls0 += sc[nt][0] + sc[nt][1];
            ls1 += sc[nt][2] + sc[nt][3];
        }
        ls0 += __shfl_xor_sync(0xffffffffu, ls0, 1);
        ls0 += __shfl_xor_sync(0xffffffffu, ls0, 2);
        ls1 += __shfl_xor_sync(0xffffffffu, ls1, 1);
        ls1 += __shfl_xor_sync(0xffffffffu, ls1, 2);
        l0 = l0 * f0 + ls0;
        l1 = l1 * f1 + ls1;

#pragma unroll
        for (int ot = 0; ot < 16; ++ot) {
            o[ot][0] *= f0; o[ot][1] *= f0;
            o[ot][2] *= f1; o[ot][3] *= f1;
        }

        // ---- pack P (single fp16) to A fragments ----
        uint32_t pa[4][4];
#pragma unroll
        for (int kc = 0; kc < 4; ++kc) {
            PACK2H(pa[kc][0], sc[2 * kc][1],     sc[2 * kc][0]);
            PACK2H(pa[kc][1], sc[2 * kc][3],     sc[2 * kc][2]);
            PACK2H(pa[kc][2], sc[2 * kc + 1][1], sc[2 * kc + 1][0]);
            PACK2H(pa[kc][3], sc[2 * kc + 1][3], sc[2 * kc + 1][2]);
        }

        // ---- O += P V (1-term) ----
#pragma unroll
        for (int kc = 0; kc < 4; ++kc) {
            uint32_t vrow = kc * 16 + ((lane >> 3) & 1) * 8 + (lane & 7);
#pragma unroll
            for (int nn2 = 0; nn2 < 8; ++nn2) {
                uint32_t ph = nn2 >> 2, nn = nn2 & 3;
                uint32_t voff = ph * 8192 + SW128(vrow * 128 + nn * 32 + (lane >> 4) * 16);
                uint32_t vh[4];
                LDSMT4(vh[0], vh[1], vh[2], vh[3], stg + 16384 + voff);
                int ot = nn2 * 2;
                MMA16816(o[ot],     pa[kc], vh[0], vh[1]);
                MMA16816(o[ot + 1], pa[kc], vh[2], vh[3]);
            }
        }
        __syncthreads();
    }

    // ---- epilogue: normalize + split-write y (fp16 hi/lo) ----
    const float inv0 = 1.f / l0, inv1 = 1.f / l1;
    const int row0 = qt * 64 + w * 16 + (lane >> 2);
    const size_t base0 = (((size_t)(b * Tn + row0)) * NHEAD + h) * HD;
    const size_t base1 = (((size_t)(b * Tn + row0 + 8)) * NHEAD + h) * HD;
#pragma unroll
    for (int ot = 0; ot < 16; ++ot) {
        int col = ot * 8 + (lane & 3) * 2;
        uint32_t hbits, lbits;
        pack_splith(o[ot][0] * inv0, o[ot][1] * inv0, hbits, lbits);
        *(uint32_t*)((char*)Yh + (base0 + col) * 2) = hbits;
        *(uint32_t*)((char*)Yl + (base0 + col) * 2) = lbits;
        pack_splith(o[ot][2] * inv1, o[ot][3] * inv1, hbits, lbits);
        *(uint32_t*)((char*)Yh + (base1 + col) * 2) = hbits;
        *(uint32_t*)((char*)Yl + (base1 + col) * 2) = lbits;
    }
}

// ---------------- launch ----------------
extern "C" void kernel_launch(void* const* d_in, const int* in_sizes, int n_in,
                              void* d_out, int out_size) {
    const float* x     = (const float*)d_in[0];
    const float* freqs = (const float*)d_in[1];
    const float* wq    = (const float*)d_in[2];
    const float* wk    = (const float*)d_in[3];
    const float* wv    = (const float*)d_in[4];
    const float* wo    = (const float*)d_in[5];
    float* out = (float*)d_out;

    __half *xhi, *xlo, *qhi, *qlo, *k16, *v16, *wT;
    cudaGetSymbolAddress((void**)&xhi, g_xhi);
    cudaGetSymbolAddress((void**)&xlo, g_xlo);
    cudaGetSymbolAddress((void**)&qhi, g_qhi);
    cudaGetSymbolAddress((void**)&qlo, g_qlo);
    cudaGetSymbolAddress((void**)&k16, g_k16);
    cudaGetSymbolAddress((void**)&v16, g_v16);
    cudaGetSymbolAddress((void**)&wT, g_wT);

    const int M = Bn * Tn;   // 8192
    const size_t xN = (size_t)M * Cn;

    cudaFuncSetAttribute(gemm2_kernel<0>, cudaFuncAttributeMaxDynamicSharedMemorySize, GM_SMEM);
    cudaFuncSetAttribute(gemm2_kernel<1>, cudaFuncAttributeMaxDynamicSharedMemorySize, GM_SMEM);
    cudaFuncSetAttribute(gemm2_kernel<2>, cudaFuncAttributeMaxDynamicSharedMemorySize, GM_SMEM);
    cudaFuncSetAttribute(gemm2_kernel<3>, cudaFuncAttributeMaxDynamicSharedMemorySize, GM_SMEM);
    cudaFuncSetAttribute(flash2_kernel, cudaFuncAttributeMaxDynamicSharedMemorySize, FL_SMEM);

    const float qscale = 0.08838834764831845f * 1.4426950408889634f;  // 1/sqrt(128)*log2(e)

    // launches 1-5
    fsplit_kernel<<<1024, 256>>>(x, xhi, xlo, xN);
    wT_kernel<<<dim3(2048 / 32, 2048 / 32), dim3(32, 8)>>>(wq, wT + WQ_OFF, GK, 2048);
    wT_kernel<<<dim3(512 / 32,  2048 / 32), dim3(32, 8)>>>(wk, wT + WK_OFF, GK, 512);
    wT_kernel<<<dim3(512 / 32,  2048 / 32), dim3(32, 8)>>>(wv, wT + WV_OFF, GK, 512);
    wT_kernel<<<dim3(2048 / 32, 2048 / 32), dim3(32, 8)>>>(wo, wT + WO_OFF, GK, 2048);

    // launch 6 (ncu-profiled): Q projection, fused RoPE+scale+split
    gemm2_kernel<1><<<dim3(16, M / 128), 256, GM_SMEM>>>(xhi, xlo, wT + WQ_OFF,
                                                         nullptr, qhi, qlo, 2048, freqs, qscale);
    // 7-8: K (RoPE) and V projections
    gemm2_kernel<2><<<dim3(4, M / 128), 256, GM_SMEM>>>(xhi, xlo, wT + WK_OFF,
                                                        nullptr, k16, nullptr, 512, freqs, 1.0f);
    gemm2_kernel<3><<<dim3(4, M / 128), 256, GM_SMEM>>>(xhi, xlo, wT + WV_OFF,
                                                        nullptr, v16, nullptr, 512, nullptr, 1.0f);

    // 9: flash attention -> y split (reuses x-split buffers)
    flash2_kernel<<<dim3(Tn / 64, Bn * NHEAD), 128, FL_SMEM>>>(qhi, qlo, k16, v16, xhi, xlo);

    // 10: output projection (f32 out)
    gemm2_kernel<0><<<dim3(16, M / 128), 256, GM_SMEM>>>(xhi, xlo, wT + WO_OFF,
                                                         out, nullptr, nullptr, 2048, nullptr, 1.0f);
}

// round 13
// speedup vs baseline: 1.0841x; 1.0841x over previous
#include <cuda_runtime.h>
#include <cuda_fp16.h>
#include <math.h>
#include <stdint.h>

#define Bn 4
#define Tn 2048
#define Cn 2048
#define NHEAD 16
#define NKV 4
#define HD 128
#define NREP 4
#define GK 2048

// ---------------- scratch (device globals) ----------------
__device__ __half g_xhi[(size_t)Bn * Tn * Cn];   // x-split; reused as y-split after flash
__device__ __half g_xlo[(size_t)Bn * Tn * Cn];
__device__ __half g_qhi[(size_t)Bn * Tn * Cn];
__device__ __half g_qlo[(size_t)Bn * Tn * Cn];
__device__ __half g_k16[(size_t)Bn * Tn * NKV * HD];
__device__ __half g_v16[(size_t)Bn * Tn * NKV * HD];

#define WQ_OFF ((size_t)0)
#define WK_OFF ((size_t)2048 * 2048)
#define WV_OFF (WK_OFF + (size_t)512 * 2048)
#define WO_OFF (WV_OFF + (size_t)512 * 2048)
#define WT_TOTAL (WO_OFF + (size_t)2048 * 2048)
__device__ __half g_wT[WT_TOTAL];

// ================= base-ISA helpers =================
__device__ __forceinline__ uint32_t smem_u32(const void* p) {
    uint32_t a;
    asm("{ .reg .u64 t; cvta.to.shared.u64 t, %1; cvt.u32.u64 %0, t; }" : "=r"(a) : "l"(p));
    return a;
}
__device__ __forceinline__ void cp16(uint32_t dst, const void* src) {
    asm volatile("cp.async.cg.shared.global [%0], [%1], 16;" :: "r"(dst), "l"(src) : "memory");
}
__device__ __forceinline__ void cp_commit() { asm volatile("cp.async.commit_group;" ::: "memory"); }
__device__ __forceinline__ void cp_wait0()  { asm volatile("cp.async.wait_group 0;" ::: "memory"); }
__device__ __forceinline__ void cp_wait1()  { asm volatile("cp.async.wait_group 1;" ::: "memory"); }
__device__ __forceinline__ float ex2f(float x) {
    float r; asm("ex2.approx.ftz.f32 %0, %1;" : "=f"(r) : "f"(x)); return r;
}

#define SW128(o) ((o) ^ (((o) >> 3) & 0x70))

#define LDSM4(r0, r1, r2, r3, addr)                                             \
    asm volatile("ldmatrix.sync.aligned.m8n8.x4.shared.b16 {%0,%1,%2,%3}, [%4];" \
                 : "=r"(r0), "=r"(r1), "=r"(r2), "=r"(r3) : "r"(addr))

#define LDSMT4(r0, r1, r2, r3, addr)                                            \
    asm volatile("ldmatrix.sync.aligned.m8n8.x4.trans.shared.b16 {%0,%1,%2,%3}, [%4];" \
                 : "=r"(r0), "=r"(r1), "=r"(r2), "=r"(r3) : "r"(addr))

#define MMA16816(d, a, b0, b1)                                                  \
    asm volatile("mma.sync.aligned.m16n8k16.row.col.f32.f16.f16.f32 "           \
                 "{%0,%1,%2,%3},{%4,%5,%6,%7},{%8,%9},{%0,%1,%2,%3};"           \
                 : "+f"((d)[0]), "+f"((d)[1]), "+f"((d)[2]), "+f"((d)[3])       \
                 : "r"((a)[0]), "r"((a)[1]), "r"((a)[2]), "r"((a)[3]),          \
                   "r"(b0), "r"(b1))

#define PACK2H(r, hiv, lov) \
    asm("cvt.rn.f16x2.f32 %0, %1, %2;" : "=r"(r) : "f"(hiv), "f"(lov))

__device__ __forceinline__ void pack_splith(float p0, float p1, uint32_t& h, uint32_t& l) {
    PACK2H(h, p1, p0);
    float h0 = __half2float(__ushort_as_half((unsigned short)(h & 0xffffu)));
    float h1 = __half2float(__ushort_as_half((unsigned short)(h >> 16)));
    PACK2H(l, p1 - h1, p0 - h0);
}

// ================= conversion kernels =================
__global__ void fsplit_kernel(const float* __restrict__ a, __half* __restrict__ hi,
                              __half* __restrict__ lo, size_t n) {
    size_t i = (size_t)blockIdx.x * blockDim.x + threadIdx.x;
    size_t stride = (size_t)gridDim.x * blockDim.x;
    for (; i < n; i += stride) {
        float v = a[i];
        __half h = __float2half_rn(v);
        hi[i] = h;
        lo[i] = __float2half_rn(v - __half2float(h));
    }
}

__global__ void wT_kernel(const float* __restrict__ w, __half* __restrict__ wT, int K, int N) {
    __shared__ float tile[32][33];
    int n0 = blockIdx.x * 32;
    int k0 = blockIdx.y * 32;
    int tx = threadIdx.x, ty = threadIdx.y;
#pragma unroll
    for (int i = ty; i < 32; i += 8)
        tile[i][tx] = w[(size_t)(k0 + i) * N + n0 + tx];
    __syncthreads();
#pragma unroll
    for (int i = ty; i < 32; i += 8)
        wT[(size_t)(n0 + i) * K + k0 + tx] = __float2half_rn(tile[tx][i]);
}

// ================= warp-MMA GEMM, 2-term (A-split x B-single), fused epilogues =======
// MODE 0: f32 out. MODE 1: RoPE+scale+split fp16. MODE 2: RoPE+single fp16. MODE 3: single fp16.
#define KCH 64
#define NCHUNK (GK / KCH)
#define TILEB (128 * 128)
#define STAGEB (3 * TILEB)
#define GM_SMEM (2 * STAGEB)              // 96 KB

template<int MODE>
__global__ __launch_bounds__(256, 2)
void gemm2_kernel(const __half* __restrict__ Ahi, const __half* __restrict__ Alo,
                  const __half* __restrict__ Bt,
                  float* __restrict__ Cf, __half* __restrict__ Ch, __half* __restrict__ Cl,
                  int Nld, const float* __restrict__ fc, float scale) {
    extern __shared__ char smem[];
    const uint32_t sb = smem_u32(smem);
    const int tid = threadIdx.x;
    const int wid = tid >> 5, lane = tid & 31;
    const int wm = wid >> 1, wn = wid & 1;
    const int m0 = blockIdx.y * 128;
    const int n0 = blockIdx.x * 128;

    const int cr = tid >> 1, chalf = tid & 1;
    const char* srcA_h = (const char*)(Ahi + (size_t)(m0 + cr) * GK);
    const char* srcA_l = (const char*)(Alo + (size_t)(m0 + cr) * GK);
    const char* srcB   = (const char*)(Bt  + (size_t)(n0 + cr) * GK);

    auto load_chunk = [&](int kc, int stage) {
        uint32_t base = sb + stage * STAGEB;
        size_t go = (size_t)kc * 128 + chalf * 64;
#pragma unroll
        for (int s = 0; s < 4; ++s) {
            uint32_t off = SW128((uint32_t)(cr * 128 + chalf * 64 + s * 16));
            cp16(base + off,             srcA_h + go + s * 16);
            cp16(base + TILEB + off,     srcA_l + go + s * 16);
            cp16(base + 2 * TILEB + off, srcB   + go + s * 16);
        }
        cp_commit();
    };

    float acc[2][8][4];
#pragma unroll
    for (int mt = 0; mt < 2; ++mt)
#pragma unroll
        for (int nt = 0; nt < 8; ++nt)
#pragma unroll
            for (int e = 0; e < 4; ++e) acc[mt][nt][e] = 0.f;

    load_chunk(0, 0);

    for (int i = 0; i < NCHUNK; ++i) {
        const int stage = i & 1;
        if (i + 1 < NCHUNK) { load_chunk(i + 1, (i + 1) & 1); cp_wait1(); }
        else                { cp_wait0(); }
        __syncthreads();

        const uint32_t bA_h = sb + stage * STAGEB;
        const uint32_t bA_l = bA_h + TILEB;
        const uint32_t bB   = bA_h + 2 * TILEB;

#pragma unroll
        for (int kk = 0; kk < 4; ++kk) {
            uint32_t ah[2][4], al[2][4];
#pragma unroll
            for (int mt = 0; mt < 2; ++mt) {
                uint32_t row = wm * 32 + mt * 16 + (lane & 15);
                uint32_t off = SW128(row * 128u + kk * 32u + ((lane >> 4) << 4));
                LDSM4(ah[mt][0], ah[mt][1], ah[mt][2], ah[mt][3], bA_h + off);
                LDSM4(al[mt][0], al[mt][1], al[mt][2], al[mt][3], bA_l + off);
            }
#pragma unroll
            for (int ntp = 0; ntp < 4; ++ntp) {
                uint32_t q = lane >> 3;
                uint32_t row = wn * 64 + ntp * 16 + ((q >> 1) << 3) + (lane & 7);
                uint32_t off = SW128(row * 128u + kk * 32u + ((q & 1) << 4));
                uint32_t bh[4];
                LDSM4(bh[0], bh[1], bh[2], bh[3], bB + off);
#pragma unroll
                for (int mt = 0; mt < 2; ++mt) {
#pragma unroll
                    for (int j = 0; j < 2; ++j) {
                        int nt = ntp * 2 + j;
                        MMA16816(acc[mt][nt], ah[mt], bh[2 * j], bh[2 * j + 1]);
                        MMA16816(acc[mt][nt], al[mt], bh[2 * j], bh[2 * j + 1]);
                    }
                }
            }
        }
        __syncthreads();
    }

    const int groupID = lane >> 2, tid4 = lane & 3;
#pragma unroll
    for (int mt = 0; mt < 2; ++mt) {
#pragma unroll
        for (int nt = 0; nt < 8; ++nt) {
            int row = m0 + wm * 32 + mt * 16 + groupID;
            int col = n0 + wn * 64 + nt * 8 + tid4 * 2;
            float v0a = acc[mt][nt][0], v1a = acc[mt][nt][1];
            float v0b = acc[mt][nt][2], v1b = acc[mt][nt][3];
            if (MODE == 0) {
                *(float2*)&Cf[(size_t)row * Nld + col]       = make_float2(v0a, v1a);
                *(float2*)&Cf[(size_t)(row + 8) * Nld + col] = make_float2(v0b, v1b);
            } else {
                if (MODE == 1 || MODE == 2) {
                    int p = (col & 127) >> 1;
                    int t0 = row & (Tn - 1);
                    float2 cs0 = *(const float2*)(fc + ((size_t)t0 * 64 + p) * 2);
                    float2 cs1 = *(const float2*)(fc + ((size_t)(t0 + 8) * 64 + p) * 2);
                    float r0 = (v0a * cs0.x - v1a * cs0.y) * scale;
                    float r1 = (v0a * cs0.y + v1a * cs0.x) * scale;
                    v0a = r0; v1a = r1;
                    r0 = (v0b * cs1.x - v1b * cs1.y) * scale;
                    r1 = (v0b * cs1.y + v1b * cs1.x) * scale;
                    v0b = r0; v1b = r1;
                }
                size_t o0 = ((size_t)row * Nld + col) * 2;
                size_t o1 = ((size_t)(row + 8) * Nld + col) * 2;
                if (MODE == 1) {
                    uint32_t hbits, lbits;
                    pack_splith(v0a, v1a, hbits, lbits);
                    *(uint32_t*)((char*)Ch + o0) = hbits;
                    *(uint32_t*)((char*)Cl + o0) = lbits;
                    pack_splith(v0b, v1b, hbits, lbits);
                    *(uint32_t*)((char*)Ch + o1) = hbits;
                    *(uint32_t*)((char*)Cl + o1) = lbits;
                } else {
                    uint32_t hb;
                    PACK2H(hb, v1a, v0a);
                    *(uint32_t*)((char*)Ch + o0) = hb;
                    PACK2H(hb, v1b, v0b);
                    *(uint32_t*)((char*)Ch + o1) = hb;
                }
            }
        }
    }
}

// ================= tensor-core flash attention (fp16; QK 2-term, PV 1-term) ===========
// Br=128 (8 warps x 16 rows), Bc=64, 256 threads, 1 CTA/SM  (R11-proven structure).
// smem: Qh 32KB @0, Ql 32KB @32768; stages @65536: { K 16KB, V 16KB } x 2 = 64KB.
#define FL_STG 32768
#define FL_SMEM (65536 + 2 * FL_STG)   // 131072

__global__ __launch_bounds__(256, 1)
void flash2_kernel(const __half* __restrict__ qh_, const __half* __restrict__ ql_,
                   const __half* __restrict__ k_, const __half* __restrict__ v_,
                   __half* __restrict__ Yh, __half* __restrict__ Yl) {
    extern __shared__ char smf[];
    const uint32_t sb = smem_u32(smf);
    const int tid = threadIdx.x;
    const int lane = tid & 31, w = tid >> 5;
    const int qt = gridDim.x - 1 - blockIdx.x;   // heavy causal tiles first
    const int bh = blockIdx.y;
    const int b = bh >> 4, h = bh & 15, g = h >> 2;

    // ---- async load Q (128 rows x 128 fp16, hi+lo) ----
    {
        int r = tid >> 1, half = tid & 1;
        size_t rowg = (size_t)(b * Tn + qt * 128 + r);
        const char* sqh = (const char*)(qh_ + (rowg * NHEAD + h) * HD + half * 64);
        const char* sql = (const char*)(ql_ + (rowg * NHEAD + h) * HD + half * 64);
        uint32_t dstH = sb + half * 16384;
        uint32_t dstL = sb + 32768 + half * 16384;
#pragma unroll
        for (int s = 0; s < 8; ++s) {
            uint32_t o = SW128((uint32_t)(r * 128 + s * 16));
            cp16(dstH + o, sqh + s * 16);
            cp16(dstL + o, sql + s * 16);
        }
    }

    const int cr = tid >> 2, cq = tid & 3;
    auto loadkv = [&](int kt, int st) {
        size_t rowg = (size_t)(b * Tn + kt * 64 + cr);
        size_t eo = (rowg * NKV + g) * HD + cq * 32;
        const char* sK = (const char*)(k_ + eo);
        const char* sV = (const char*)(v_ + eo);
        uint32_t base = sb + 65536 + st * FL_STG + (cq >> 1) * 8192;
#pragma unroll
        for (int s = 0; s < 4; ++s) {
            uint32_t o = SW128((uint32_t)(cr * 128 + (cq & 1) * 64 + s * 16));
            cp16(base + o,         sK + s * 16);
            cp16(base + 16384 + o, sV + s * 16);
        }
        cp_commit();
    };

    float o[16][4];
#pragma unroll
    for (int i = 0; i < 16; ++i)
#pragma unroll
        for (int e = 0; e < 4; ++e) o[i][e] = 0.f;
    float m0 = -1e30f, m1 = -1e30f, l0 = 0.f, l1 = 0.f;

    loadkv(0, 0);
    const int nch = 2 * qt + 2;

    for (int kt = 0; kt < nch; ++kt) {
        const int st = kt & 1;
        if (kt + 1 < nch) { loadkv(kt + 1, (kt + 1) & 1); cp_wait1(); }
        else              { cp_wait0(); }
        __syncthreads();

        const uint32_t stg = sb + 65536 + st * FL_STG;

        // ---- S = Q K^T (2-term: Qh*K + Ql*K) ----
        float sc[8][4];
#pragma unroll
        for (int nt = 0; nt < 8; ++nt)
#pragma unroll
            for (int e = 0; e < 4; ++e) sc[nt][e] = 0.f;

#pragma unroll
        for (int kk = 0; kk < 8; ++kk) {
            const uint32_t panel = kk >> 2;
            const uint32_t pb = (kk & 3) * 32;
            uint32_t arow = w * 16 + ((lane >> 3) & 1) * 8 + (lane & 7);
            uint32_t aoff = panel * 16384 + SW128(arow * 128 + pb + (lane >> 4) * 16);
            uint32_t ah[4], al[4];
            LDSM4(ah[0], ah[1], ah[2], ah[3], sb + aoff);
            LDSM4(al[0], al[1], al[2], al[3], sb + 32768 + aoff);
#pragma unroll
            for (int nq = 0; nq < 4; ++nq) {
                uint32_t krow = nq * 16 + (lane >> 4) * 8 + (lane & 7);
                uint32_t koff = panel * 8192 + SW128(krow * 128 + pb + ((lane >> 3) & 1) * 16);
                uint32_t kh[4];
                LDSM4(kh[0], kh[1], kh[2], kh[3], stg + koff);
                MMA16816(sc[2 * nq],     ah, kh[0], kh[1]);
                MMA16816(sc[2 * nq],     al, kh[0], kh[1]);
                MMA16816(sc[2 * nq + 1], ah, kh[2], kh[3]);
                MMA16816(sc[2 * nq + 1], al, kh[2], kh[3]);
            }
        }

        // ---- causal mask (diag chunks only) ----
        if (kt >= 2 * qt) {
            const int qi0 = qt * 128 + w * 16 + (lane >> 2);
            const int cb = kt * 64 + (lane & 3) * 2;
#pragma unroll
            for (int nt = 0; nt < 8; ++nt) {
#pragma unroll
                for (int e = 0; e < 4; ++e) {
                    int col = cb + nt * 8 + (e & 1);
                    int qi = qi0 + (e >> 1) * 8;
                    if (col > qi) sc[nt][e] = -1e30f;
                }
            }
        }

        // ---- online softmax (log2 domain) ----
        float mx0 = -1e30f, mx1 = -1e30f;
#pragma unroll
        for (int nt = 0; nt < 8; ++nt) {
            mx0 = fmaxf(mx0, fmaxf(sc[nt][0], sc[nt][1]));
            mx1 = fmaxf(mx1, fmaxf(sc[nt][2], sc[nt][3]));
        }
        mx0 = fmaxf(mx0, __shfl_xor_sync(0xffffffffu, mx0, 1));
        mx0 = fmaxf(mx0, __shfl_xor_sync(0xffffffffu, mx0, 2));
        mx1 = fmaxf(mx1, __shfl_xor_sync(0xffffffffu, mx1, 1));
        mx1 = fmaxf(mx1, __shfl_xor_sync(0xffffffffu, mx1, 2));

        float mn0 = fmaxf(m0, mx0), mn1 = fmaxf(m1, mx1);
        float f0 = ex2f(m0 - mn0), f1 = ex2f(m1 - mn1);
        m0 = mn0; m1 = mn1;

        float ls0 = 0.f, ls1 = 0.f;
#pragma unroll
        for (int nt = 0; nt < 8; ++nt) {
            sc[nt][0] = ex2f(sc[nt][0] - m0);
            sc[nt][1] = ex2f(sc[nt][1] - m0);
            sc[nt][2] = ex2f(sc[nt][2] - m1);
            sc[nt][3] = ex2f(sc[nt][3] - m1);
            ls0 += sc[nt][0] + sc[nt][1];
            ls1 += sc[nt][2] + sc[nt][3];
        }
        ls0 += __shfl_xor_sync(0xffffffffu, ls0, 1);
        ls0 += __shfl_xor_sync(0xffffffffu, ls0, 2);
        ls1 += __shfl_xor_sync(0xffffffffu, ls1, 1);
        ls1 += __shfl_xor_sync(0xffffffffu, ls1, 2);
        l0 = l0 * f0 + ls0;
        l1 = l1 * f1 + ls1;

#pragma unroll
        for (int ot = 0; ot < 16; ++ot) {
            o[ot][0] *= f0; o[ot][1] *= f0;
            o[ot][2] *= f1; o[ot][3] *= f1;
        }

        // ---- pack P (single fp16) to A fragments ----
        uint32_t pa[4][4];
#pragma unroll
        for (int kc = 0; kc < 4; ++kc) {
            PACK2H(pa[kc][0], sc[2 * kc][1],     sc[2 * kc][0]);
            PACK2H(pa[kc][1], sc[2 * kc][3],     sc[2 * kc][2]);
            PACK2H(pa[kc][2], sc[2 * kc + 1][1], sc[2 * kc + 1][0]);
            PACK2H(pa[kc][3], sc[2 * kc + 1][3], sc[2 * kc + 1][2]);
        }

        // ---- O += P V (1-term) ----
#pragma unroll
        for (int kc = 0; kc < 4; ++kc) {
            uint32_t vrow = kc * 16 + ((lane >> 3) & 1) * 8 + (lane & 7);
#pragma unroll
            for (int nn2 = 0; nn2 < 8; ++nn2) {
                uint32_t ph = nn2 >> 2, nn = nn2 & 3;
                uint32_t voff = ph * 8192 + SW128(vrow * 128 + nn * 32 + (lane >> 4) * 16);
                uint32_t vh[4];
                LDSMT4(vh[0], vh[1], vh[2], vh[3], stg + 16384 + voff);
                int ot = nn2 * 2;
                MMA16816(o[ot],     pa[kc], vh[0], vh[1]);
                MMA16816(o[ot + 1], pa[kc], vh[2], vh[3]);
            }
        }
        __syncthreads();
    }

    // ---- epilogue: normalize + split-write y (fp16 hi/lo) ----
    const float inv0 = 1.f / l0, inv1 = 1.f / l1;
    const int row0 = qt * 128 + w * 16 + (lane >> 2);
    const size_t base0 = (((size_t)(b * Tn + row0)) * NHEAD + h) * HD;
    const size_t base1 = (((size_t)(b * Tn + row0 + 8)) * NHEAD + h) * HD;
#pragma unroll
    for (int ot = 0; ot < 16; ++ot) {
        int col = ot * 8 + (lane & 3) * 2;
        uint32_t hbits, lbits;
        pack_splith(o[ot][0] * inv0, o[ot][1] * inv0, hbits, lbits);
        *(uint32_t*)((char*)Yh + (base0 + col) * 2) = hbits;
        *(uint32_t*)((char*)Yl + (base0 + col) * 2) = lbits;
        pack_splith(o[ot][2] * inv1, o[ot][3] * inv1, hbits, lbits);
        *(uint32_t*)((char*)Yh + (base1 + col) * 2) = hbits;
        *(uint32_t*)((char*)Yl + (base1 + col) * 2) = lbits;
    }
}

// ---------------- launch ----------------
extern "C" void kernel_launch(void* const* d_in, const int* in_sizes, int n_in,
                              void* d_out, int out_size) {
    const float* x     = (const float*)d_in[0];
    const float* freqs = (const float*)d_in[1];
    const float* wq    = (const float*)d_in[2];
    const float* wk    = (const float*)d_in[3];
    const float* wv    = (const float*)d_in[4];
    const float* wo    = (const float*)d_in[5];
    float* out = (float*)d_out;

    __half *xhi, *xlo, *qhi, *qlo, *k16, *v16, *wT;
    cudaGetSymbolAddress((void**)&xhi, g_xhi);
    cudaGetSymbolAddress((void**)&xlo, g_xlo);
    cudaGetSymbolAddress((void**)&qhi, g_qhi);
    cudaGetSymbolAddress((void**)&qlo, g_qlo);
    cudaGetSymbolAddress((void**)&k16, g_k16);
    cudaGetSymbolAddress((void**)&v16, g_v16);
    cudaGetSymbolAddress((void**)&wT, g_wT);

    const int M = Bn * Tn;   // 8192
    const size_t xN = (size_t)M * Cn;

    cudaFuncSetAttribute(gemm2_kernel<0>, cudaFuncAttributeMaxDynamicSharedMemorySize, GM_SMEM);
    cudaFuncSetAttribute(gemm2_kernel<1>, cudaFuncAttributeMaxDynamicSharedMemorySize, GM_SMEM);
    cudaFuncSetAttribute(gemm2_kernel<2>, cudaFuncAttributeMaxDynamicSharedMemorySize, GM_SMEM);
    cudaFuncSetAttribute(gemm2_kernel<3>, cudaFuncAttributeMaxDynamicSharedMemorySize, GM_SMEM);
    cudaFuncSetAttribute(flash2_kernel, cudaFuncAttributeMaxDynamicSharedMemorySize, FL_SMEM);

    const float qscale = 0.08838834764831845f * 1.4426950408889634f;  // 1/sqrt(128)*log2(e)

    // launches 1-5
    fsplit_kernel<<<1024, 256>>>(x, xhi, xlo, xN);
    wT_kernel<<<dim3(2048 / 32, 2048 / 32), dim3(32, 8)>>>(wq, wT + WQ_OFF, GK, 2048);
    wT_kernel<<<dim3(512 / 32,  2048 / 32), dim3(32, 8)>>>(wk, wT + WK_OFF, GK, 512);
    wT_kernel<<<dim3(512 / 32,  2048 / 32), dim3(32, 8)>>>(wv, wT + WV_OFF, GK, 512);
    wT_kernel<<<dim3(2048 / 32, 2048 / 32), dim3(32, 8)>>>(wo, wT + WO_OFF, GK, 2048);

    // launch 6 (ncu-profiled): Q projection, fused RoPE+scale+split
    gemm2_kernel<1><<<dim3(16, M / 128), 256, GM_SMEM>>>(xhi, xlo, wT + WQ_OFF,
                                                         nullptr, qhi, qlo, 2048, freqs, qscale);
    // 7-8: K (RoPE) and V projections
    gemm2_kernel<2><<<dim3(4, M / 128), 256, GM_SMEM>>>(xhi, xlo, wT + WK_OFF,
                                                        nullptr, k16, nullptr, 512, freqs, 1.0f);
    gemm2_kernel<3><<<dim3(4, M / 128), 256, GM_SMEM>>>(xhi, xlo, wT + WV_OFF,
                                                        nullptr, v16, nullptr, 512, nullptr, 1.0f);

    // 9: flash attention -> y split (reuses x-split buffers)
    flash2_kernel<<<dim3(Tn / 128, Bn * NHEAD), 256, FL_SMEM>>>(qhi, qlo, k16, v16, xhi, xlo);

    // 10: output projection (f32 out)
    gemm2_kernel<0><<<dim3(16, M / 128), 256, GM_SMEM>>>(xhi, xlo, wT + WO_OFF,
                                                         out, nullptr, nullptr, 2048, nullptr, 1.0f);
}